// round 16
// baseline (speedup 1.0000x reference)
#include <cuda_runtime.h>
#include <cuda_bf16.h>
#include <cstdint>

#define NB 65536
#define FEAT 261
#define HID 128
#define KSTEPS 17                  // K padded to 272
#define NTILES 17                  // 136 cols: 128 Wc1 + 7 gates + 1 pad col
#define NTHREAD 512
#define ROWS_CTA 256
#define CHUNK 64
#define NCHUNK 4
#define NCTA (NB / ROWS_CTA)       // 256

// W fragment scratch: [kstep][tile][lane][4 u32 = bh0,bh1,bl0,bl1]
#define WFRAG_U32 (KSTEPS * NTILES * 32 * 4)   // 36992 u32 = 147968 B
__device__ __align__(16) uint32_t g_wfrag[WFRAG_U32];

// ---- smem layout ----
#define P_LEAF 0       // 64 floats
#define P_BC1  64      // 128
#define P_WC2  192     // 128
#define P_B    320     // 8
#define P_VBUF 328     // 2 bufs x 4 nq x 64 rows = 512
#define P_GBUF 840     // 2 bufs x 64 x 8 = 1024
#define PARAM_FLOATS 1872
#define OFF_WF  (PARAM_FLOATS * 4)             // 7488
#define OFF_XHI (OFF_WF + WFRAG_U32 * 4)       // 155456
#define XSTRIDE_B 560                          // 140 u32/row: ldmatrix conflict-free
#define XBUF_B (CHUNK * XSTRIDE_B)             // 35840
#define OFF_XLO (OFF_XHI + XBUF_B)
#define SMEM_BYTES (OFF_XLO + XBUF_B)          // 227136  (< 232448 limit)

// ======================= prep: extended W -> interleaved bf16 hi/lo fragments =======================
__device__ __forceinline__ float wgate_val(int j, int k, const float* w0,
                                           const float* w1, const float* w2) {
    if (k >= FEAT) return 0.0f;
    if (j == 0) return w0[k];
    if (j < 3) {
        int nd = j - 1;
        if (k < 5) return w1[nd * 133 + k];
        int lo = 5 + nd * 128;
        if (k >= lo && k < lo + 128) return w1[nd * 133 + 5 + (k - lo)];
        return 0.0f;
    }
    if (j < 7) {
        int nd = j - 3;
        if (k < 5) return w2[nd * 69 + k];
        int lo = 5 + nd * 64;
        if (k >= lo && k < lo + 64) return w2[nd * 69 + 5 + (k - lo)];
        return 0.0f;
    }
    return 0.0f;
}

__global__ void __launch_bounds__(256) prep_w(const float* __restrict__ Wc1,
                                              const float* __restrict__ w0,
                                              const float* __restrict__ w1,
                                              const float* __restrict__ w2) {
    int idx = blockIdx.x * 256 + threadIdx.x;
    if (idx >= WFRAG_U32) return;
    int j    = idx & 3;
    int lane = (idx >> 2) & 31;
    int tt   = (idx >> 7) % NTILES;
    int s    = (idx >> 7) / NTILES;
    int n = tt * 8 + (lane >> 2);
    int k = s * 16 + (j & 1) * 8 + (lane & 3) * 2;

    float v0, v1;
    if (n < HID) {
        v0 = (k     < FEAT) ? Wc1[k * HID + n]       : 0.0f;
        v1 = (k + 1 < FEAT) ? Wc1[(k + 1) * HID + n] : 0.0f;
    } else {
        int jc = n - HID;
        v0 = wgate_val(jc, k,     w0, w1, w2);
        v1 = wgate_val(jc, k + 1, w0, w1, w2);
    }
    __nv_bfloat16 h0 = __float2bfloat16(v0), h1 = __float2bfloat16(v1);
    if (j < 2) {
        g_wfrag[idx] = ((uint32_t)__bfloat16_as_ushort(h1) << 16) | __bfloat16_as_ushort(h0);
    } else {
        __nv_bfloat16 l0 = __float2bfloat16(v0 - __bfloat162float(h0));
        __nv_bfloat16 l1 = __float2bfloat16(v1 - __bfloat162float(h1));
        g_wfrag[idx] = ((uint32_t)__bfloat16_as_ushort(l1) << 16) | __bfloat16_as_ushort(l0);
    }
}

// ======================= helpers =======================
__device__ __forceinline__ float sigmoidf_fast(float g) { return 1.0f / (1.0f + __expf(-g)); }

__device__ __forceinline__ uint32_t smem_u32(const void* p) {
    uint32_t a;
    asm("{ .reg .u64 t; cvta.to.shared.u64 t, %1; cvt.u32.u64 %0, t; }" : "=r"(a) : "l"(p));
    return a;
}

__device__ __forceinline__ uint32_t split_pair(float v0, float v1, uint32_t& lo) {
    uint32_t b0 = __float_as_uint(v0), b1 = __float_as_uint(v1), hi;
    asm("prmt.b32 %0, %1, %2, 0x7632;" : "=r"(hi) : "r"(b0), "r"(b1));
    float t0 = __uint_as_float(b0 & 0xFFFF0000u);
    float t1 = __uint_as_float(b1 & 0xFFFF0000u);
    float l0 = v0 - t0, l1 = v1 - t1;
    asm("cvt.rn.bf16x2.f32 %0, %1, %2;" : "=r"(lo) : "f"(l1), "f"(l0));
    return hi;
}

#define MMA16816(c, a, b0, b1) \
    asm volatile("mma.sync.aligned.m16n8k16.row.col.f32.bf16.bf16.f32 " \
        "{%0,%1,%2,%3}, {%4,%5,%6,%7}, {%8,%9}, {%0,%1,%2,%3};" \
        : "+f"((c)[0]), "+f"((c)[1]), "+f"((c)[2]), "+f"((c)[3]) \
        : "r"((a)[0]), "r"((a)[1]), "r"((a)[2]), "r"((a)[3]), "r"(b0), "r"(b1))

#define LDSM4(r, addr) \
    asm volatile("ldmatrix.sync.aligned.m8n8.x4.shared.b16 {%0,%1,%2,%3}, [%4];" \
        : "=r"((r)[0]), "=r"((r)[1]), "=r"((r)[2]), "=r"((r)[3]) : "r"(addr))

// ======================= main fused kernel =======================
__global__ void __launch_bounds__(NTHREAD, 1)
ac_main(const float* __restrict__ x,
        const float* __restrict__ w0, const float* __restrict__ b0,
        const float* __restrict__ w1, const float* __restrict__ b1,
        const float* __restrict__ w2, const float* __restrict__ b2,
        const float* __restrict__ leaf,
        const float* __restrict__ bc1,
        const float* __restrict__ Wc2, const float* __restrict__ bc2,
        float* __restrict__ p_out, float* __restrict__ v_out)
{
    extern __shared__ char smem[];
    float* sp = (float*)smem;
    const uint32_t smem_base = smem_u32(smem);
    const int tid  = threadIdx.x;
    const int lane = tid & 31;
    const int warp = tid >> 5;      // 0..15
    const int nq   = warp & 3;      // tiles nq*4 .. nq*4+3
    const int mt   = warp >> 2;     // 0..3 (16 rows within chunk)
    const int row0 = blockIdx.x * ROWS_CTA;

    // staging indices
    const int srow = tid >> 3;      // 0..63
    const int sq   = tid & 7;       // pair-quad offset

    uint32_t* xh = (uint32_t*)(smem + OFF_XHI);
    uint32_t* xl = (uint32_t*)(smem + OFF_XLO);

    // ---- register prefetch of a chunk's x (17 float2 per thread) ----
    float2 pf[17];
    auto ldg_chunk = [&](int c) {
        const float* xr = x + (size_t)(row0 + c * CHUNK + srow) * FEAT;
        #pragma unroll
        for (int j = 0; j < 17; j++) {
            const int k = sq * 2 + 16 * j;
            float a = (k     < FEAT) ? xr[k]     : 0.0f;
            float b = (k + 1 < FEAT) ? xr[k + 1] : 0.0f;
            pf[j] = make_float2(a, b);
        }
    };
    auto sts_chunk = [&]() {
        const int ob = srow * 140 + sq;
        #pragma unroll
        for (int j = 0; j < 17; j++) {
            uint32_t lo;
            uint32_t hi = split_pair(pf[j].x, pf[j].y, lo);
            xh[ob + 8 * j] = hi;
            xl[ob + 8 * j] = lo;
        }
    };

    // ---- preamble: params, W fragments, chunk 0 ----
    ldg_chunk(0);
    if (tid < 64)  sp[P_LEAF + tid] = leaf[tid];
    if (tid >= 64  && tid < 192) sp[P_BC1 + tid - 64]  = bc1[tid - 64];
    if (tid >= 192 && tid < 320) sp[P_WC2 + tid - 192] = Wc2[tid - 192];
    if (tid == 320) {
        sp[P_B + 0] = b0[0];
        sp[P_B + 1] = b1[0]; sp[P_B + 2] = b1[1];
        sp[P_B + 3] = b2[0]; sp[P_B + 4] = b2[1]; sp[P_B + 5] = b2[2]; sp[P_B + 6] = b2[3];
        sp[P_B + 7] = bc2[0];
    }
    for (int i = tid; i < 1024; i += NTHREAD) sp[P_GBUF + i] = 0.0f;  // both gate bufs
    {
        const uint4* g = (const uint4*)g_wfrag;
        uint4* s = (uint4*)(smem + OFF_WF);
        #pragma unroll 4
        for (int i = tid; i < WFRAG_U32 / 4; i += NTHREAD) s[i] = g[i];
    }
    sts_chunk();
    __syncthreads();

    const uint4* wf = (const uint4*)(smem + OFF_WF);
    const uint32_t a_hi0 = smem_base + OFF_XHI
        + (uint32_t)((mt * 16 + (lane & 15)) * XSTRIDE_B + ((lane >> 4) & 1) * 16);

    #pragma unroll 1
    for (int c = 0; c < NCHUNK; c++) {
        if (c < NCHUNK - 1) ldg_chunk(c + 1);   // LDG latency hides under GEMM

        // ---- GEMM chunk c: warp = m16 x tiles [nq*4, nq*4+4) (+ gate pass for nq>=1) ----
        float acc[4][4] = {};
        float accg[4] = {0, 0, 0, 0};
        uint32_t ah[4], al[4];
        uint32_t a_addr = a_hi0;
        LDSM4(ah, a_addr);
        LDSM4(al, a_addr + XBUF_B);

        const uint4* bp = wf + (size_t)(nq * 4) * 32 + lane;
        const uint4* gpnt = wf + (size_t)16 * 32 + lane;

        #pragma unroll 1
        for (int s = 0; s < KSTEPS; s++) {
            uint32_t nh[4], nl[4];
            if (s < KSTEPS - 1) {
                LDSM4(nh, a_addr + 32);
                LDSM4(nl, a_addr + 32 + XBUF_B);
            }
            const uint4 b0 = bp[0];
            const uint4 b1 = bp[32];
            const uint4 b2 = bp[64];
            const uint4 b3 = bp[96];
            // hi * W_hi (dep stride 4)
            MMA16816(acc[0], ah, b0.x, b0.y);
            MMA16816(acc[1], ah, b1.x, b1.y);
            MMA16816(acc[2], ah, b2.x, b2.y);
            MMA16816(acc[3], ah, b3.x, b3.y);
            // lo * W_hi
            MMA16816(acc[0], al, b0.x, b0.y);
            MMA16816(acc[1], al, b1.x, b1.y);
            MMA16816(acc[2], al, b2.x, b2.y);
            MMA16816(acc[3], al, b3.x, b3.y);
            // hi * W_lo
            MMA16816(acc[0], ah, b0.z, b0.w);
            MMA16816(acc[1], ah, b1.z, b1.w);
            MMA16816(acc[2], ah, b2.z, b2.w);
            MMA16816(acc[3], ah, b3.z, b3.w);
            // gate tile: one pass per nq in {1,2,3}
            if (nq == 1) {
                const uint4 bg = gpnt[0];
                MMA16816(accg, ah, bg.x, bg.y);
            } else if (nq == 2) {
                const uint4 bg = gpnt[0];
                MMA16816(accg, al, bg.x, bg.y);
            } else if (nq == 3) {
                const uint4 bg = gpnt[0];
                MMA16816(accg, ah, bg.z, bg.w);
            }
            bp += NTILES * 32;
            gpnt += NTILES * 32;
            a_addr += 32;
            #pragma unroll
            for (int p = 0; p < 4; p++) { ah[p] = nh[p]; al[p] = nl[p]; }
        }

        // ---- chunk epilogue: v partials + gate partials (double-buffered) ----
        const int buf = c & 1;
        {
            float p0 = 0.0f, p1 = 0.0f;
            #pragma unroll
            for (int t = 0; t < 4; t++) {
                const int c0 = (nq * 4 + t) * 8 + (lane & 3) * 2;
                const float b0v = sp[P_BC1 + c0],     w0v = sp[P_WC2 + c0];
                const float b1v = sp[P_BC1 + c0 + 1], w1v = sp[P_WC2 + c0 + 1];
                p0 = fmaf(fmaxf(acc[t][0] + b0v, 0.0f), w0v, p0);
                p0 = fmaf(fmaxf(acc[t][1] + b1v, 0.0f), w1v, p0);
                p1 = fmaf(fmaxf(acc[t][2] + b0v, 0.0f), w0v, p1);
                p1 = fmaf(fmaxf(acc[t][3] + b1v, 0.0f), w1v, p1);
            }
            p0 += __shfl_xor_sync(0xffffffffu, p0, 1);
            p0 += __shfl_xor_sync(0xffffffffu, p0, 2);
            p1 += __shfl_xor_sync(0xffffffffu, p1, 1);
            p1 += __shfl_xor_sync(0xffffffffu, p1, 2);
            const int r = mt * 16 + (lane >> 2);
            if ((lane & 3) == 0) {
                sp[P_VBUF + buf * 256 + nq * 64 + r]     = p0;
                sp[P_VBUF + buf * 256 + nq * 64 + r + 8] = p1;
            }
            if (nq >= 1) {
                const int cc = (lane & 3) * 2;
                float* gb = sp + P_GBUF + buf * 512;
                atomicAdd(&gb[r * 8 + cc],           accg[0]);
                atomicAdd(&gb[r * 8 + cc + 1],       accg[1]);
                atomicAdd(&gb[(r + 8) * 8 + cc],     accg[2]);
                atomicAdd(&gb[(r + 8) * 8 + cc + 1], accg[3]);
            }
        }
        __syncthreads();

        // ---- post region: STS next chunk; zero other gate buf (ALL 512 entries); outputs ----
        if (c < NCHUNK - 1) {
            sts_chunk();
            sp[P_GBUF + (1 - buf) * 512 + tid] = 0.0f;   // 512 threads cover all 512 entries
        }

        if (tid < CHUNK) {
            const int row = row0 + c * CHUNK + tid;
            const float* g = sp + P_GBUF + buf * 512 + tid * 8;
            float g0 = g[0] + sp[P_B + 0];
            int n0 = (g0 >= 0.0f) ? 1 : 0;
            float g1 = g[1 + n0] + sp[P_B + 1 + n0];
            int n1 = n0 * 2 + ((g1 >= 0.0f) ? 1 : 0);
            float g2 = g[3 + n1] + sp[P_B + 3 + n1];
            int node = n1 * 2 + ((g2 >= 0.0f) ? 1 : 0);

            if (fminf(fminf(fabsf(g0), fabsf(g1)), fabsf(g2)) < 1e-3f) {
                // exact fp32 recompute of the path (rare); weights from global (L2-hot)
                const float* xrow = x + (size_t)row * FEAT;
                g0 = sp[P_B + 0];
                for (int k = 0; k < FEAT; k++) g0 = fmaf(xrow[k], w0[k], g0);
                n0 = (g0 >= 0.0f) ? 1 : 0;
                {
                    const float* wr = w1 + n0 * 133;
                    g1 = sp[P_B + 1 + n0];
                    for (int k = 0; k < 5; k++) g1 = fmaf(xrow[k], wr[k], g1);
                    const int off = 5 + n0 * 128;
                    for (int k = 0; k < 128; k++) g1 = fmaf(xrow[off + k], wr[5 + k], g1);
                }
                n1 = n0 * 2 + ((g1 >= 0.0f) ? 1 : 0);
                {
                    const float* wr = w2 + n1 * 69;
                    g2 = sp[P_B + 3 + n1];
                    for (int k = 0; k < 5; k++) g2 = fmaf(xrow[k], wr[k], g2);
                    const int off = 5 + n1 * 64;
                    for (int k = 0; k < 64; k++) g2 = fmaf(xrow[off + k], wr[5 + k], g2);
                }
                node = n1 * 2 + ((g2 >= 0.0f) ? 1 : 0);
            }

            const float cum = sigmoidf_fast(g0) * sigmoidf_fast(g1) * sigmoidf_fast(g2);
            const float* lf = sp + P_LEAF + node * 8;
            float4 o0 = make_float4(cum*lf[0], cum*lf[1], cum*lf[2], cum*lf[3]);
            float4 o1 = make_float4(cum*lf[4], cum*lf[5], cum*lf[6], cum*lf[7]);
            ((float4*)(p_out + (size_t)row * 8))[0] = o0;
            ((float4*)(p_out + (size_t)row * 8))[1] = o1;

            const float* vb = sp + P_VBUF + buf * 256;
            v_out[row] = vb[tid] + vb[64 + tid] + vb[128 + tid] + vb[192 + tid] + sp[P_B + 7];
        }
        __syncthreads();
    }
}

extern "C" void kernel_launch(void* const* d_in, const int* in_sizes, int n_in,
                              void* d_out, int out_size) {
    (void)in_sizes; (void)n_in; (void)out_size;
    const float* x    = (const float*)d_in[0];
    const float* w0   = (const float*)d_in[1];
    const float* b0   = (const float*)d_in[2];
    const float* w1   = (const float*)d_in[3];
    const float* b1   = (const float*)d_in[4];
    const float* w2   = (const float*)d_in[5];
    const float* b2   = (const float*)d_in[6];
    const float* leaf = (const float*)d_in[7];
    const float* Wc1  = (const float*)d_in[8];
    const float* bc1  = (const float*)d_in[9];
    const float* Wc2  = (const float*)d_in[10];
    const float* bc2  = (const float*)d_in[11];

    float* out   = (float*)d_out;
    float* p_out = out;
    float* v_out = out + (size_t)NB * 8;

    prep_w<<<(WFRAG_U32 + 255) / 256, 256>>>(Wc1, w0, w1, w2);

    cudaFuncSetAttribute(ac_main, cudaFuncAttributeMaxDynamicSharedMemorySize, SMEM_BYTES);
    ac_main<<<NCTA, NTHREAD, SMEM_BYTES>>>(
        x, w0, b0, w1, b1, w2, b2, leaf, bc1, Wc2, bc2, p_out, v_out);
}

// round 17
// speedup vs baseline: 1.5792x; 1.5792x over previous
#include <cuda_runtime.h>
#include <cuda_bf16.h>
#include <cstdint>

#define NB 65536
#define FEAT 261
#define HID 128
#define KSTEPS 17                  // K padded to 272
#define NTILES 17                  // 136 cols: 128 Wc1 + 7 gates + 1 pad col
#define NTHREAD 512
#define ROWS_CTA 256
#define CHUNK 64
#define NCHUNK 4
#define NCTA (NB / ROWS_CTA)       // 256

// W fragment scratch: [kstep][tile][lane][4 u32 = bh0,bh1,bl0,bl1]
#define WFRAG_U32 (KSTEPS * NTILES * 32 * 4)   // 36992 u32 = 147968 B
__device__ __align__(16) uint32_t g_wfrag[WFRAG_U32];

// ---- smem layout ----
#define P_LEAF 0       // 64 floats
#define P_BC1  64      // 128
#define P_WC2  192     // 128
#define P_B    320     // 8
#define P_VBUF 328     // 2 bufs x 4 nq x 64 rows = 512
#define P_GBUF 840     // 2 bufs x 64 x 8 = 1024
#define PARAM_FLOATS 1872
#define OFF_WF  (PARAM_FLOATS * 4)             // 7488
#define OFF_XHI (OFF_WF + WFRAG_U32 * 4)       // 155456
#define XSTRIDE_B 560                          // 140 u32/row: ldmatrix conflict-free
#define XBUF_B (CHUNK * XSTRIDE_B)             // 35840
#define OFF_XLO (OFF_XHI + XBUF_B)
#define SMEM_BYTES (OFF_XLO + XBUF_B)          // 227136

// ======================= prep: extended W -> interleaved bf16 hi/lo fragments =======================
__device__ __forceinline__ float wgate_val(int j, int k, const float* w0,
                                           const float* w1, const float* w2) {
    if (k >= FEAT) return 0.0f;
    if (j == 0) return w0[k];
    if (j < 3) {
        int nd = j - 1;
        if (k < 5) return w1[nd * 133 + k];
        int lo = 5 + nd * 128;
        if (k >= lo && k < lo + 128) return w1[nd * 133 + 5 + (k - lo)];
        return 0.0f;
    }
    if (j < 7) {
        int nd = j - 3;
        if (k < 5) return w2[nd * 69 + k];
        int lo = 5 + nd * 64;
        if (k >= lo && k < lo + 64) return w2[nd * 69 + 5 + (k - lo)];
        return 0.0f;
    }
    return 0.0f;
}

__global__ void __launch_bounds__(256) prep_w(const float* __restrict__ Wc1,
                                              const float* __restrict__ w0,
                                              const float* __restrict__ w1,
                                              const float* __restrict__ w2) {
    int idx = blockIdx.x * 256 + threadIdx.x;
    if (idx >= WFRAG_U32) return;
    int j    = idx & 3;
    int lane = (idx >> 2) & 31;
    int tt   = (idx >> 7) % NTILES;
    int s    = (idx >> 7) / NTILES;
    int n = tt * 8 + (lane >> 2);
    int k = s * 16 + (j & 1) * 8 + (lane & 3) * 2;

    float v0, v1;
    if (n < HID) {
        v0 = (k     < FEAT) ? Wc1[k * HID + n]       : 0.0f;
        v1 = (k + 1 < FEAT) ? Wc1[(k + 1) * HID + n] : 0.0f;
    } else {
        int jc = n - HID;
        v0 = wgate_val(jc, k,     w0, w1, w2);
        v1 = wgate_val(jc, k + 1, w0, w1, w2);
    }
    __nv_bfloat16 h0 = __float2bfloat16(v0), h1 = __float2bfloat16(v1);
    if (j < 2) {
        g_wfrag[idx] = ((uint32_t)__bfloat16_as_ushort(h1) << 16) | __bfloat16_as_ushort(h0);
    } else {
        __nv_bfloat16 l0 = __float2bfloat16(v0 - __bfloat162float(h0));
        __nv_bfloat16 l1 = __float2bfloat16(v1 - __bfloat162float(h1));
        g_wfrag[idx] = ((uint32_t)__bfloat16_as_ushort(l1) << 16) | __bfloat16_as_ushort(l0);
    }
}

// ======================= helpers =======================
__device__ __forceinline__ float sigmoidf_fast(float g) { return 1.0f / (1.0f + __expf(-g)); }

__device__ __forceinline__ uint32_t smem_u32(const void* p) {
    uint32_t a;
    asm("{ .reg .u64 t; cvta.to.shared.u64 t, %1; cvt.u32.u64 %0, t; }" : "=r"(a) : "l"(p));
    return a;
}

__device__ __forceinline__ uint32_t split_pair(float v0, float v1, uint32_t& lo) {
    uint32_t b0 = __float_as_uint(v0), b1 = __float_as_uint(v1), hi;
    asm("prmt.b32 %0, %1, %2, 0x7632;" : "=r"(hi) : "r"(b0), "r"(b1));
    float t0 = __uint_as_float(b0 & 0xFFFF0000u);
    float t1 = __uint_as_float(b1 & 0xFFFF0000u);
    float l0 = v0 - t0, l1 = v1 - t1;
    asm("cvt.rn.bf16x2.f32 %0, %1, %2;" : "=r"(lo) : "f"(l1), "f"(l0));
    return hi;
}

#define MMA16816(c, a, b0, b1) \
    asm volatile("mma.sync.aligned.m16n8k16.row.col.f32.bf16.bf16.f32 " \
        "{%0,%1,%2,%3}, {%4,%5,%6,%7}, {%8,%9}, {%0,%1,%2,%3};" \
        : "+f"((c)[0]), "+f"((c)[1]), "+f"((c)[2]), "+f"((c)[3]) \
        : "r"((a)[0]), "r"((a)[1]), "r"((a)[2]), "r"((a)[3]), "r"(b0), "r"(b1))

#define LDSM4(r, addr) \
    asm volatile("ldmatrix.sync.aligned.m8n8.x4.shared.b16 {%0,%1,%2,%3}, [%4];" \
        : "=r"((r)[0]), "=r"((r)[1]), "=r"((r)[2]), "=r"((r)[3]) : "r"(addr))

// ======================= main fused kernel =======================
__global__ void __launch_bounds__(NTHREAD, 1)
ac_main(const float* __restrict__ x,
        const float* __restrict__ w0, const float* __restrict__ b0,
        const float* __restrict__ w1, const float* __restrict__ b1,
        const float* __restrict__ w2, const float* __restrict__ b2,
        const float* __restrict__ leaf,
        const float* __restrict__ bc1,
        const float* __restrict__ Wc2, const float* __restrict__ bc2,
        float* __restrict__ p_out, float* __restrict__ v_out)
{
    extern __shared__ char smem[];
    float* sp = (float*)smem;
    const uint32_t smem_base = smem_u32(smem);
    const int tid  = threadIdx.x;
    const int lane = tid & 31;
    const int warp = tid >> 5;      // 0..15
    const int nq   = warp & 3;      // tiles nq*4 .. nq*4+3
    const int mt   = warp >> 2;     // 0..3 (16 rows within chunk)
    const int row0 = blockIdx.x * ROWS_CTA;

    const int srow = tid >> 3;      // 0..63
    const int sq   = tid & 7;

    uint32_t* xh = (uint32_t*)(smem + OFF_XHI);
    uint32_t* xl = (uint32_t*)(smem + OFF_XLO);

    // ---- two-batch staging (9 + 8 float2; peak 18 regs) ----
    float2 pf[9];
    auto ldg_b1 = [&](int c) {
        const float* xr = x + (size_t)(row0 + c * CHUNK + srow) * FEAT;
        #pragma unroll
        for (int j = 0; j < 9; j++) {
            const int k = sq * 2 + 16 * j;   // max 142 < FEAT, no guard needed
            pf[j] = make_float2(xr[k], xr[k + 1]);
        }
    };
    auto sts_b1 = [&]() {
        const int ob = srow * 140 + sq;
        #pragma unroll
        for (int j = 0; j < 9; j++) {
            uint32_t lo;
            uint32_t hi = split_pair(pf[j].x, pf[j].y, lo);
            xh[ob + 8 * j] = hi;
            xl[ob + 8 * j] = lo;
        }
    };
    auto ldg_b2 = [&](int c) {
        const float* xr = x + (size_t)(row0 + c * CHUNK + srow) * FEAT;
        #pragma unroll
        for (int j = 0; j < 8; j++) {
            const int k = sq * 2 + 16 * (9 + j);
            float a = (k     < FEAT) ? xr[k]     : 0.0f;
            float b = (k + 1 < FEAT) ? xr[k + 1] : 0.0f;
            pf[j] = make_float2(a, b);
        }
    };
    auto sts_b2 = [&]() {
        const int ob = srow * 140 + sq;
        #pragma unroll
        for (int j = 0; j < 8; j++) {
            uint32_t lo;
            uint32_t hi = split_pair(pf[j].x, pf[j].y, lo);
            xh[ob + 8 * (9 + j)] = hi;
            xl[ob + 8 * (9 + j)] = lo;
        }
    };

    // ---- preamble ----
    ldg_b1(0);
    if (tid < 64)  sp[P_LEAF + tid] = leaf[tid];
    if (tid >= 64  && tid < 192) sp[P_BC1 + tid - 64]  = bc1[tid - 64];
    if (tid >= 192 && tid < 320) sp[P_WC2 + tid - 192] = Wc2[tid - 192];
    if (tid == 320) {
        sp[P_B + 0] = b0[0];
        sp[P_B + 1] = b1[0]; sp[P_B + 2] = b1[1];
        sp[P_B + 3] = b2[0]; sp[P_B + 4] = b2[1]; sp[P_B + 5] = b2[2]; sp[P_B + 6] = b2[3];
        sp[P_B + 7] = bc2[0];
    }
    for (int i = tid; i < 1024; i += NTHREAD) sp[P_GBUF + i] = 0.0f;
    {
        const uint4* g = (const uint4*)g_wfrag;
        uint4* s = (uint4*)(smem + OFF_WF);
        #pragma unroll 4
        for (int i = tid; i < WFRAG_U32 / 4; i += NTHREAD) s[i] = g[i];
    }
    sts_b1();
    ldg_b2(0);
    sts_b2();
    __syncthreads();

    const uint4* wf = (const uint4*)(smem + OFF_WF);
    const uint32_t a_hi0 = smem_base + OFF_XHI
        + (uint32_t)((mt * 16 + (lane & 15)) * XSTRIDE_B + ((lane >> 4) & 1) * 16);

    float acc[4][4];
    float accg[4];

    auto do_mmas = [&](int s, const uint32_t* ah, const uint32_t* al) {
        const uint4* bp = wf + (size_t)(s * NTILES + nq * 4) * 32 + lane;
        const uint4 b0 = bp[0];
        const uint4 b1 = bp[32];
        const uint4 b2 = bp[64];
        const uint4 b3 = bp[96];
        MMA16816(acc[0], ah, b0.x, b0.y);
        MMA16816(acc[1], ah, b1.x, b1.y);
        MMA16816(acc[2], ah, b2.x, b2.y);
        MMA16816(acc[3], ah, b3.x, b3.y);
        MMA16816(acc[0], al, b0.x, b0.y);
        MMA16816(acc[1], al, b1.x, b1.y);
        MMA16816(acc[2], al, b2.x, b2.y);
        MMA16816(acc[3], al, b3.x, b3.y);
        MMA16816(acc[0], ah, b0.z, b0.w);
        MMA16816(acc[1], ah, b1.z, b1.w);
        MMA16816(acc[2], ah, b2.z, b2.w);
        MMA16816(acc[3], ah, b3.z, b3.w);
        if (nq == 1) {
            const uint4 bg = wf[(size_t)(s * NTILES + 16) * 32 + lane];
            MMA16816(accg, ah, bg.x, bg.y);
        } else if (nq == 2) {
            const uint4 bg = wf[(size_t)(s * NTILES + 16) * 32 + lane];
            MMA16816(accg, al, bg.x, bg.y);
        } else if (nq == 3) {
            const uint4 bg = wf[(size_t)(s * NTILES + 16) * 32 + lane];
            MMA16816(accg, ah, bg.z, bg.w);
        }
    };

    #pragma unroll 1
    for (int c = 0; c < NCHUNK; c++) {
        if (c < NCHUNK - 1) ldg_b1(c + 1);   // batch1 LDG latency hides under GEMM

        #pragma unroll
        for (int t = 0; t < 4; t++)
            #pragma unroll
            for (int j = 0; j < 4; j++) acc[t][j] = 0.0f;
        #pragma unroll
        for (int j = 0; j < 4; j++) accg[j] = 0.0f;

        // ---- GEMM: s-loop unrolled x2, ping-pong A fragments ----
        uint32_t aA[4], lA[4], aB[4], lB[4];
        LDSM4(aA, a_hi0);
        LDSM4(lA, a_hi0 + XBUF_B);
        #pragma unroll 1
        for (int s = 0; s < 16; s += 2) {
            LDSM4(aB, a_hi0 + (uint32_t)((s + 1) * 32));
            LDSM4(lB, a_hi0 + (uint32_t)((s + 1) * 32) + XBUF_B);
            do_mmas(s, aA, lA);
            LDSM4(aA, a_hi0 + (uint32_t)((s + 2) * 32));
            LDSM4(lA, a_hi0 + (uint32_t)((s + 2) * 32) + XBUF_B);
            do_mmas(s + 1, aB, lB);
        }
        do_mmas(16, aA, lA);

        // ---- chunk epilogue: v partials + gate partials ----
        const int buf = c & 1;
        {
            float p0 = 0.0f, p1 = 0.0f;
            #pragma unroll
            for (int t = 0; t < 4; t++) {
                const int c0 = (nq * 4 + t) * 8 + (lane & 3) * 2;
                const float b0v = sp[P_BC1 + c0],     w0v = sp[P_WC2 + c0];
                const float b1v = sp[P_BC1 + c0 + 1], w1v = sp[P_WC2 + c0 + 1];
                p0 = fmaf(fmaxf(acc[t][0] + b0v, 0.0f), w0v, p0);
                p0 = fmaf(fmaxf(acc[t][1] + b1v, 0.0f), w1v, p0);
                p1 = fmaf(fmaxf(acc[t][2] + b0v, 0.0f), w0v, p1);
                p1 = fmaf(fmaxf(acc[t][3] + b1v, 0.0f), w1v, p1);
            }
            p0 += __shfl_xor_sync(0xffffffffu, p0, 1);
            p0 += __shfl_xor_sync(0xffffffffu, p0, 2);
            p1 += __shfl_xor_sync(0xffffffffu, p1, 1);
            p1 += __shfl_xor_sync(0xffffffffu, p1, 2);
            const int r = mt * 16 + (lane >> 2);
            if ((lane & 3) == 0) {
                sp[P_VBUF + buf * 256 + nq * 64 + r]     = p0;
                sp[P_VBUF + buf * 256 + nq * 64 + r + 8] = p1;
            }
            if (nq >= 1) {
                const int cc = (lane & 3) * 2;
                float* gb = sp + P_GBUF + buf * 512;
                atomicAdd(&gb[r * 8 + cc],           accg[0]);
                atomicAdd(&gb[r * 8 + cc + 1],       accg[1]);
                atomicAdd(&gb[(r + 8) * 8 + cc],     accg[2]);
                atomicAdd(&gb[(r + 8) * 8 + cc + 1], accg[3]);
            }
        }
        __syncthreads();

        // ---- post region: stage next chunk; zero other gate buf; outputs ----
        if (c < NCHUNK - 1) {
            sts_b1();
            ldg_b2(c + 1);
            sts_b2();
            sp[P_GBUF + (1 - buf) * 512 + tid] = 0.0f;
        }

        if (tid < CHUNK) {
            const int row = row0 + c * CHUNK + tid;
            const float* g = sp + P_GBUF + buf * 512 + tid * 8;
            float g0 = g[0] + sp[P_B + 0];
            int n0 = (g0 >= 0.0f) ? 1 : 0;
            float g1 = g[1 + n0] + sp[P_B + 1 + n0];
            int n1 = n0 * 2 + ((g1 >= 0.0f) ? 1 : 0);
            float g2 = g[3 + n1] + sp[P_B + 3 + n1];
            int node = n1 * 2 + ((g2 >= 0.0f) ? 1 : 0);

            if (fminf(fminf(fabsf(g0), fabsf(g1)), fabsf(g2)) < 1e-3f) {
                // exact fp32 recompute of the path (rare); weights from global
                const float* xrow = x + (size_t)row * FEAT;
                g0 = sp[P_B + 0];
                for (int k = 0; k < FEAT; k++) g0 = fmaf(xrow[k], w0[k], g0);
                n0 = (g0 >= 0.0f) ? 1 : 0;
                {
                    const float* wr = w1 + n0 * 133;
                    g1 = sp[P_B + 1 + n0];
                    for (int k = 0; k < 5; k++) g1 = fmaf(xrow[k], wr[k], g1);
                    const int off = 5 + n0 * 128;
                    for (int k = 0; k < 128; k++) g1 = fmaf(xrow[off + k], wr[5 + k], g1);
                }
                n1 = n0 * 2 + ((g1 >= 0.0f) ? 1 : 0);
                {
                    const float* wr = w2 + n1 * 69;
                    g2 = sp[P_B + 3 + n1];
                    for (int k = 0; k < 5; k++) g2 = fmaf(xrow[k], wr[k], g2);
                    const int off = 5 + n1 * 64;
                    for (int k = 0; k < 64; k++) g2 = fmaf(xrow[off + k], wr[5 + k], g2);
                }
                node = n1 * 2 + ((g2 >= 0.0f) ? 1 : 0);
            }

            const float cum = sigmoidf_fast(g0) * sigmoidf_fast(g1) * sigmoidf_fast(g2);
            const float* lf = sp + P_LEAF + node * 8;
            float4 o0 = make_float4(cum*lf[0], cum*lf[1], cum*lf[2], cum*lf[3]);
            float4 o1 = make_float4(cum*lf[4], cum*lf[5], cum*lf[6], cum*lf[7]);
            ((float4*)(p_out + (size_t)row * 8))[0] = o0;
            ((float4*)(p_out + (size_t)row * 8))[1] = o1;

            const float* vb = sp + P_VBUF + buf * 256;
            v_out[row] = vb[tid] + vb[64 + tid] + vb[128 + tid] + vb[192 + tid] + sp[P_B + 7];
        }
        __syncthreads();
    }
}

extern "C" void kernel_launch(void* const* d_in, const int* in_sizes, int n_in,
                              void* d_out, int out_size) {
    (void)in_sizes; (void)n_in; (void)out_size;
    const float* x    = (const float*)d_in[0];
    const float* w0   = (const float*)d_in[1];
    const float* b0   = (const float*)d_in[2];
    const float* w1   = (const float*)d_in[3];
    const float* b1   = (const float*)d_in[4];
    const float* w2   = (const float*)d_in[5];
    const float* b2   = (const float*)d_in[6];
    const float* leaf = (const float*)d_in[7];
    const float* Wc1  = (const float*)d_in[8];
    const float* bc1  = (const float*)d_in[9];
    const float* Wc2  = (const float*)d_in[10];
    const float* bc2  = (const float*)d_in[11];

    float* out   = (float*)d_out;
    float* p_out = out;
    float* v_out = out + (size_t)NB * 8;

    prep_w<<<(WFRAG_U32 + 255) / 256, 256>>>(Wc1, w0, w1, w2);

    cudaFuncSetAttribute(ac_main, cudaFuncAttributeMaxDynamicSharedMemorySize, SMEM_BYTES);
    ac_main<<<NCTA, NTHREAD, SMEM_BYTES>>>(
        x, w0, b0, w1, b1, w2, b2, leaf, bc1, Wc2, bc2, p_out, v_out);
}